// round 11
// baseline (speedup 1.0000x reference)
#include <cuda_runtime.h>

// ---------------- problem constants (fixed shapes) ----------------
#define Bc 2
#define Nc 50000
#define Cc 15
#define PAIRS (Bc*Cc)          // 30
#define CS 4                   // cluster size (CTAs per (b,c) pair)
#define NPER (Nc/CS)           // 12500 candidates per CTA
#define TH 512
#define CPT 25                 // 25*512 = 12800 >= 12500
#define MAXDET 300
#define NEGV (-1e9f)
#define NK (Cc*MAXDET)         // 4500

#define DYN_BYTES (CPT*TH*16)  // 204800 B box cache
#define FIN_BYTES (NK*12)      // keys (8B) + idx (4B)

typedef unsigned long long u64;

// scratch (no allocations allowed -> __device__ globals)
__device__ int   g_pick_idx[PAIRS*MAXDET];
__device__ float g_pick_score[PAIRS*MAXDET];

// pack (score, index) into a u64 so that max() == (higher score, then LOWER index)
__device__ __forceinline__ u64 packkey(float s, unsigned int gidx){
    unsigned int sb = __float_as_uint(s);
    sb = (sb & 0x80000000u) ? ~sb : (sb | 0x80000000u);   // monotone float->uint
    return ((u64)sb << 32) | (unsigned int)(~gidx);
}
__device__ __forceinline__ float unpackscore(u64 k){
    unsigned int sb = (unsigned int)(k >> 32);
    return (sb & 0x80000000u) ? __uint_as_float(sb ^ 0x80000000u)
                              : __uint_as_float(~sb);
}
__device__ __forceinline__ u64 umax(u64 a, u64 b){ return a > b ? a : b; }
__device__ __forceinline__ u64 umin(u64 a, u64 b){ return a > b ? b : a; }

// branchless sorted-desc insert into quad
__device__ __forceinline__ void top4ins(u64 kk, u64 &q1, u64 &q2, u64 &q3, u64 &q4){
    bool g1 = kk > q1, g2 = kk > q2, g3 = kk > q3, g4 = kk > q4;
    q4 = g4 ? (g3 ? q3 : kk) : q4;
    q3 = g3 ? (g2 ? q2 : kk) : q3;
    q2 = g2 ? (g1 ? q1 : kk) : q2;
    q1 = g1 ? kk : q1;
}
// merge sorted-desc quads across the warp (butterfly); all lanes converge
__device__ __forceinline__ void warp_top4(u64 &q1, u64 &q2, u64 &q3, u64 &q4){
    #pragma unroll
    for (int o = 16; o; o >>= 1){
        u64 o1 = __shfl_xor_sync(0xFFFFFFFFu, q1, o);
        u64 o2 = __shfl_xor_sync(0xFFFFFFFFu, q2, o);
        u64 o3 = __shfl_xor_sync(0xFFFFFFFFu, q3, o);
        u64 o4 = __shfl_xor_sync(0xFFFFFFFFu, q4, o);
        // bitonic exchange (top half of 8) then bitonic-sort-4 desc
        u64 L1 = umax(q1, o4), L2 = umax(q2, o3), L3 = umax(q3, o2), L4 = umax(q4, o1);
        u64 a = umax(L1, L3), c = umin(L1, L3);
        u64 b = umax(L2, L4), d = umin(L2, L4);
        q1 = umax(a, b); q2 = umin(a, b); q3 = umax(c, d); q4 = umin(c, d);
    }
}

extern __shared__ float4 s_boxes[];

__global__ void __cluster_dims__(CS,1,1) __launch_bounds__(TH,1)
nms_kernel(const float* __restrict__ boxes, const float* __restrict__ cls)
{
    __shared__ u64 s_wq[16][4];
    __shared__ u64 s_key [2][CS][4];   // double-buffered cluster exchange (sorted quads)
    __shared__ __align__(16) float4 s_pbox[2][CS][4];
    __shared__ u64 s_mbar[2];

    const int pair = blockIdx.x >> 2;
    const int rank = blockIdx.x & 3;
    const int b = pair / Cc;
    const int c = pair % Cc;
    const int base = rank * NPER;
    const int t = threadIdx.x;

    const float4* gbox = reinterpret_cast<const float4*>(boxes) + (size_t)b * Nc;

    if (t == 0){
        unsigned int m0 = (unsigned int)__cvta_generic_to_shared(&s_mbar[0]);
        unsigned int m1 = (unsigned int)__cvta_generic_to_shared(&s_mbar[1]);
        asm volatile("mbarrier.init.shared.b64 [%0], %1;" :: "r"(m0), "r"(CS) : "memory");
        asm volatile("mbarrier.init.shared.b64 [%0], %1;" :: "r"(m1), "r"(CS) : "memory");
    }

    // ---- load this CTA's boxes into SMEM (coalesced); zero OOB tail ----
    for (int i = t; i < NPER; i += TH) s_boxes[i] = gbox[base + i];
    for (int i = NPER + t; i < CPT*TH; i += TH) s_boxes[i] = make_float4(0.f,0.f,0.f,0.f);

    // ---- load + threshold scores into registers ----
    float sc[CPT];
    #pragma unroll
    for (int k = 0; k < CPT; k++){
        int li = k*TH + t;
        float s = NEGV;
        if (li < NPER){
            float v = cls[((size_t)(b*Nc + base + li))*Cc + c];
            if (v > 0.05f) s = v;
        }
        sc[k] = s;
    }
    __syncthreads();

    // cluster sync: mbarrier inits visible cluster-wide before any remote arrive
    asm volatile("barrier.cluster.arrive.aligned;" ::: "memory");
    asm volatile("barrier.cluster.wait.aligned;"   ::: "memory");

    // ---- initial per-thread top-4 ----
    u64 q1 = 0ull, q2 = 0ull, q3 = 0ull, q4 = 0ull;
    #pragma unroll
    for (int k = 0; k < CPT; k++)
        top4ins(packkey(sc[k], (unsigned)(base + k*TH + t)), q1, q2, q3, q4);

    // exact IoU(pivot P with area pa, candidate B with area ab) > 0.5
    auto iou_gt = [](float4 P, float pa, float4 B, float ab) -> bool {
        float y1 = fmaxf(P.x, B.x), x1 = fmaxf(P.y, B.y);
        float y2 = fminf(P.z, B.z), x2 = fminf(P.w, B.w);
        float inter = fmaxf(y2 - y1, 0.f) * fmaxf(x2 - x1, 0.f);
        float denom = pa + ab - inter + 1e-9f;
        return __fdiv_rn(inter, denom) > 0.5f;
    };

    // ---- NMS rounds: 1..4 picks per round ----
    int det = 0, round = 0;
    while (det < MAXDET){
        const int pidx = round & 1;
        const unsigned par = (unsigned)((round >> 1) & 1);

        // CTA top-4 reduce
        u64 a1 = q1, a2k = q2, a3k = q3, a4k = q4;
        warp_top4(a1, a2k, a3k, a4k);
        if ((t & 31) == 0){
            s_wq[t >> 5][0] = a1; s_wq[t >> 5][1] = a2k;
            s_wq[t >> 5][2] = a3k; s_wq[t >> 5][3] = a4k;
        }
        __syncthreads();
        if (t < 32){
            u64 c1 = (t < 16) ? s_wq[t][0] : 0ull;
            u64 c2 = (t < 16) ? s_wq[t][1] : 0ull;
            u64 c3 = (t < 16) ? s_wq[t][2] : 0ull;
            u64 c4 = (t < 16) ? s_wq[t][3] : 0ull;
            warp_top4(c1, c2, c3, c4);
            if (t < CS){
                // lane r ships sorted quad (keys + boxes) to CTA r's slot[rank]
                float4 w1 = s_boxes[(~(unsigned int)c1) - (unsigned)base];
                float4 w2 = s_boxes[(~(unsigned int)c2) - (unsigned)base];
                float4 w3 = s_boxes[(~(unsigned int)c3) - (unsigned)base];
                float4 w4 = s_boxes[(~(unsigned int)c4) - (unsigned)base];
                unsigned int lkey = (unsigned int)__cvta_generic_to_shared(&s_key [pidx][rank][0]);
                unsigned int lbox = (unsigned int)__cvta_generic_to_shared(&s_pbox[pidx][rank][0]);
                unsigned int lmb  = (unsigned int)__cvta_generic_to_shared(&s_mbar[pidx]);
                unsigned int rk, rb, rm;
                asm("mapa.shared::cluster.u32 %0, %1, %2;" : "=r"(rk) : "r"(lkey), "r"(t));
                asm("mapa.shared::cluster.u32 %0, %1, %2;" : "=r"(rb) : "r"(lbox), "r"(t));
                asm("mapa.shared::cluster.u32 %0, %1, %2;" : "=r"(rm) : "r"(lmb),  "r"(t));
                asm volatile("st.shared::cluster.u64 [%0], %1;"    :: "r"(rk), "l"(c1) : "memory");
                asm volatile("st.shared::cluster.u64 [%0+8], %1;"  :: "r"(rk), "l"(c2) : "memory");
                asm volatile("st.shared::cluster.u64 [%0+16], %1;" :: "r"(rk), "l"(c3) : "memory");
                asm volatile("st.shared::cluster.u64 [%0+24], %1;" :: "r"(rk), "l"(c4) : "memory");
                u64 p01, p23;
                asm("mov.b64 %0, {%1,%2};" : "=l"(p01) : "f"(w1.x), "f"(w1.y));
                asm("mov.b64 %0, {%1,%2};" : "=l"(p23) : "f"(w1.z), "f"(w1.w));
                asm volatile("st.shared::cluster.u64 [%0], %1;"    :: "r"(rb), "l"(p01) : "memory");
                asm volatile("st.shared::cluster.u64 [%0+8], %1;"  :: "r"(rb), "l"(p23) : "memory");
                asm("mov.b64 %0, {%1,%2};" : "=l"(p01) : "f"(w2.x), "f"(w2.y));
                asm("mov.b64 %0, {%1,%2};" : "=l"(p23) : "f"(w2.z), "f"(w2.w));
                asm volatile("st.shared::cluster.u64 [%0+16], %1;" :: "r"(rb), "l"(p01) : "memory");
                asm volatile("st.shared::cluster.u64 [%0+24], %1;" :: "r"(rb), "l"(p23) : "memory");
                asm("mov.b64 %0, {%1,%2};" : "=l"(p01) : "f"(w3.x), "f"(w3.y));
                asm("mov.b64 %0, {%1,%2};" : "=l"(p23) : "f"(w3.z), "f"(w3.w));
                asm volatile("st.shared::cluster.u64 [%0+32], %1;" :: "r"(rb), "l"(p01) : "memory");
                asm volatile("st.shared::cluster.u64 [%0+40], %1;" :: "r"(rb), "l"(p23) : "memory");
                asm("mov.b64 %0, {%1,%2};" : "=l"(p01) : "f"(w4.x), "f"(w4.y));
                asm("mov.b64 %0, {%1,%2};" : "=l"(p23) : "f"(w4.z), "f"(w4.w));
                asm volatile("st.shared::cluster.u64 [%0+48], %1;" :: "r"(rb), "l"(p01) : "memory");
                asm volatile("st.shared::cluster.u64 [%0+56], %1;" :: "r"(rb), "l"(p23) : "memory");
                asm volatile("mbarrier.arrive.release.cluster.shared::cluster.b64 _, [%0];" :: "r"(rm) : "memory");
            }
        }
        // wait for all 4 CTAs (acquire orders remote stores)
        {
            unsigned int mloc = (unsigned int)__cvta_generic_to_shared(&s_mbar[pidx]);
            unsigned int done = 0;
            while (!done){
                asm volatile(
                    "{\n\t.reg .pred p;\n\t"
                    "mbarrier.try_wait.parity.acquire.cluster.shared::cta.b64 p, [%1], %2, 0x989680;\n\t"
                    "selp.b32 %0, 1, 0, p;\n\t}"
                    : "=r"(done) : "r"(mloc), "r"(par) : "memory");
            }
        }

        // ---- global top-4: 4-way merge of 4 sorted quads (identical everywhere) ----
        u64 K[4]; float4 Bx[4];
        {
            int h0 = 0, h1 = 0, h2 = 0, h3 = 0;
            #pragma unroll
            for (int j = 0; j < 4; j++){
                u64 k0 = s_key[pidx][0][h0];
                u64 k1 = s_key[pidx][1][h1];
                u64 k2 = s_key[pidx][2][h2];
                u64 k3 = s_key[pidx][3][h3];
                u64 m01 = umax(k0, k1), m23 = umax(k2, k3);
                u64 mm = umax(m01, m23);
                int r = (mm == k0) ? 0 : (mm == k1) ? 1 : (mm == k2) ? 2 : 3;
                int h = (r == 0) ? h0 : (r == 1) ? h1 : (r == 2) ? h2 : h3;
                K[j] = mm;
                Bx[j] = s_pbox[pidx][r][h];
                if (r == 0) h0++; else if (r == 1) h1++; else if (r == 2) h2++; else h3++;
            }
        }

        // ---- validation chain (exact, cluster-uniform) ----
        float4 B1 = Bx[0], B2 = Bx[1], B3 = Bx[2], B4 = Bx[3];
        float pa1 = (B1.z - B1.x) * (B1.w - B1.y);
        float ar2 = (B2.z - B2.x) * (B2.w - B2.y);
        float ar3 = (B3.z - B3.x) * (B3.w - B3.y);
        float ar4 = (B4.z - B4.x) * (B4.w - B4.y);
        float s1 = unpackscore(K[0]), s2 = unpackscore(K[1]);
        float s3 = unpackscore(K[2]), s4 = unpackscore(K[3]);

        bool acc2 = (s2 != NEGV) && (det + 1 < MAXDET) && !iou_gt(B1, pa1, B2, ar2);
        int  n2 = 1 + (acc2 ? 1 : 0);
        bool acc3 = (s3 != NEGV) && (det + n2 < MAXDET)
                    && !iou_gt(B1, pa1, B3, ar3)
                    && !(acc2 && iou_gt(B2, ar2, B3, ar3));
        int  n3 = n2 + (acc3 ? 1 : 0);
        bool acc4 = (s4 != NEGV) && (det + n3 < MAXDET)
                    && !iou_gt(B1, pa1, B4, ar4)
                    && !(acc2 && iou_gt(B2, ar2, B4, ar4))
                    && !(acc3 && iou_gt(B3, ar3, B4, ar4));
        const int npick = n3 + (acc4 ? 1 : 0);

        const unsigned int widx1 = ~((unsigned int)K[0]);
        const unsigned int widx2 = acc2 ? ~((unsigned int)K[1]) : widx1;
        const unsigned int widx3 = acc3 ? ~((unsigned int)K[2]) : widx1;
        const unsigned int widx4 = acc4 ? ~((unsigned int)K[3]) : widx1;
        float4 P2 = acc2 ? B2 : B1;  float pa2 = acc2 ? ar2 : pa1;
        float4 P3 = acc3 ? B3 : B1;  float pa3 = acc3 ? ar3 : pa1;
        float4 P4 = acc4 ? B4 : B1;  float pa4 = acc4 ? ar4 : pa1;

        if (rank == 0 && t == 0){
            int off = pair*MAXDET + det;
            g_pick_idx[off] = (int)widx1; g_pick_score[off] = s1; off++;
            if (acc2){ g_pick_idx[off] = (int)widx2; g_pick_score[off] = s2; off++; }
            if (acc3){ g_pick_idx[off] = (int)widx3; g_pick_score[off] = s3; off++; }
            if (acc4){ g_pick_idx[off] = (int)widx4; g_pick_score[off] = s4; off++; }
        }

        // per-thread winner-slot ids
        const unsigned int wl1 = widx1 - (unsigned)base;
        const unsigned int wl2 = widx2 - (unsigned)base;
        const unsigned int wl3 = widx3 - (unsigned)base;
        const unsigned int wl4 = widx4 - (unsigned)base;
        const int W1 = ((wl1 & (TH-1)) == (unsigned)t) ? (int)(wl1 >> 9) : -1;
        const int W2 = ((wl2 & (TH-1)) == (unsigned)t) ? (int)(wl2 >> 9) : -1;
        const int W3 = ((wl3 & (TH-1)) == (unsigned)t) ? (int)(wl3 >> 9) : -1;
        const int W4 = ((wl4 & (TH-1)) == (unsigned)t) ? (int)(wl4 >> 9) : -1;

        // ---- suppress pass + folded top-4 (cluster-uniform path select) ----
        unsigned band1 = 0, band2 = 0, band3 = 0, band4 = 0;
        q1 = q2 = q3 = q4 = 0ull;

        if (acc2 || acc3 || acc4){
            #pragma unroll
            for (int k = 0; k < CPT; k++){
                float s = sc[k];
                bool alive = (s != NEGV);
                float4 bx = make_float4(0.f,0.f,0.f,0.f);
                if (alive) bx = s_boxes[k*TH + t];
                float ak = (bx.z - bx.x) * (bx.w - bx.y);
                bool ab1, ab2, ab3, ab4;
                {
                    float y1 = fmaxf(B1.x, bx.x), x1 = fmaxf(B1.y, bx.y);
                    float y2 = fminf(B1.z, bx.z), x2 = fminf(B1.w, bx.w);
                    float in_ = fmaxf(y2 - y1, 0.f) * fmaxf(x2 - x1, 0.f);
                    float dn = pa1 + ak - in_ + 1e-9f;
                    float ii = in_ + in_;
                    ab1 = (ii > 1.0001f * dn);
                    band1 |= (alive && !ab1 && !(ii < 0.9999f * dn)) ? (1u << k) : 0u;
                }
                {
                    float y1 = fmaxf(P2.x, bx.x), x1 = fmaxf(P2.y, bx.y);
                    float y2 = fminf(P2.z, bx.z), x2 = fminf(P2.w, bx.w);
                    float in_ = fmaxf(y2 - y1, 0.f) * fmaxf(x2 - x1, 0.f);
                    float dn = pa2 + ak - in_ + 1e-9f;
                    float ii = in_ + in_;
                    ab2 = (ii > 1.0001f * dn);
                    band2 |= (alive && !ab2 && !(ii < 0.9999f * dn)) ? (1u << k) : 0u;
                }
                {
                    float y1 = fmaxf(P3.x, bx.x), x1 = fmaxf(P3.y, bx.y);
                    float y2 = fminf(P3.z, bx.z), x2 = fminf(P3.w, bx.w);
                    float in_ = fmaxf(y2 - y1, 0.f) * fmaxf(x2 - x1, 0.f);
                    float dn = pa3 + ak - in_ + 1e-9f;
                    float ii = in_ + in_;
                    ab3 = (ii > 1.0001f * dn);
                    band3 |= (alive && !ab3 && !(ii < 0.9999f * dn)) ? (1u << k) : 0u;
                }
                {
                    float y1 = fmaxf(P4.x, bx.x), x1 = fmaxf(P4.y, bx.y);
                    float y2 = fminf(P4.z, bx.z), x2 = fminf(P4.w, bx.w);
                    float in_ = fmaxf(y2 - y1, 0.f) * fmaxf(x2 - x1, 0.f);
                    float dn = pa4 + ak - in_ + 1e-9f;
                    float ii = in_ + in_;
                    ab4 = (ii > 1.0001f * dn);
                    band4 |= (alive && !ab4 && !(ii < 0.9999f * dn)) ? (1u << k) : 0u;
                }
                bool supf = alive && (ab1 || ab2 || ab3 || ab4 ||
                                      (k == W1) || (k == W2) || (k == W3) || (k == W4));
                float ns = supf ? NEGV : s;
                sc[k] = ns;
                top4ins(packkey(ns, (unsigned)(base + k*TH + t)), q1, q2, q3, q4);
            }
        } else {
            #pragma unroll
            for (int k = 0; k < CPT; k++){
                float s = sc[k];
                bool alive = (s != NEGV);
                float4 bx = make_float4(0.f,0.f,0.f,0.f);
                if (alive) bx = s_boxes[k*TH + t];
                float ak = (bx.z - bx.x) * (bx.w - bx.y);
                float y1 = fmaxf(B1.x, bx.x), x1 = fmaxf(B1.y, bx.y);
                float y2 = fminf(B1.z, bx.z), x2 = fminf(B1.w, bx.w);
                float in_ = fmaxf(y2 - y1, 0.f) * fmaxf(x2 - x1, 0.f);
                float dn = pa1 + ak - in_ + 1e-9f;
                float ii = in_ + in_;
                bool ab = (ii > 1.0001f * dn);
                band1 |= (alive && !ab && !(ii < 0.9999f * dn)) ? (1u << k) : 0u;
                bool supf = alive && (ab || (k == W1));
                float ns = supf ? NEGV : s;
                sc[k] = ns;
                top4ins(packkey(ns, (unsigned)(base + k*TH + t)), q1, q2, q3, q4);
            }
        }

        // rare exact-division fixup (warp-uniform outer branch); redo top-4 after
        if (__any_sync(0xFFFFFFFFu, (band1 | band2 | band3 | band4) != 0)){
            unsigned bb = band1 | band2 | band3 | band4;
            #pragma unroll
            for (int k = 0; k < CPT; k++){
                if (bb & (1u << k)){
                    float4 bx = s_boxes[k*TH + t];
                    float ak = (bx.z - bx.x) * (bx.w - bx.y);
                    bool sup = false;
                    if (band1 & (1u << k)) sup |= iou_gt(B1, pa1, bx, ak);
                    if (band2 & (1u << k)) sup |= iou_gt(P2, pa2, bx, ak);
                    if (band3 & (1u << k)) sup |= iou_gt(P3, pa3, bx, ak);
                    if (band4 & (1u << k)) sup |= iou_gt(P4, pa4, bx, ak);
                    if (sup) sc[k] = NEGV;
                }
            }
            q1 = q2 = q3 = q4 = 0ull;
            #pragma unroll
            for (int k = 0; k < CPT; k++)
                top4ins(packkey(sc[k], (unsigned)(base + k*TH + t)), q1, q2, q3, q4);
        }

        det += npick;
        round++;
    }

    // trailing sync so no CTA exits while peers may still address its SMEM
    asm volatile("barrier.cluster.arrive.aligned;" ::: "memory");
    asm volatile("barrier.cluster.wait.aligned;"   ::: "memory");
}

// ---------------- per-image top-300 via per-key global rank ----------------
extern __shared__ char f_dyn[];
__global__ void __launch_bounds__(512)
finalize_kernel(const float* __restrict__ boxes, float* __restrict__ out)
{
    u64* s_keys = reinterpret_cast<u64*>(f_dyn);
    int* s_idx = reinterpret_cast<int*>(f_dyn + NK*8);

    const int b = blockIdx.x;
    const int t = threadIdx.x;

    for (int i = t; i < NK; i += 512){
        s_keys[i] = packkey(g_pick_score[b*NK + i], (unsigned)i);
        s_idx[i]  = g_pick_idx[b*NK + i];
    }
    __syncthreads();

    const float4* gbox = reinterpret_cast<const float4*>(boxes) + (size_t)b * Nc;
    float4* obox   = reinterpret_cast<float4*>(out);
    float*  oscore = out + (size_t)Bc*MAXDET*4;
    float*  olab   = out + (size_t)Bc*MAXDET*5;

    for (int i = t; i < NK; i += 512){
        u64 my = s_keys[i];
        int rnk = 0;
        #pragma unroll
        for (int c = 0; c < Cc; c++){
            int lo = 0, hi = MAXDET;
            while (lo < hi){                       // 9 data-independent steps
                int mid = (lo + hi) >> 1;
                if (s_keys[c*MAXDET + mid] > my) lo = mid + 1; else hi = mid;
            }
            rnk += lo;
        }
        if (rnk < MAXDET){
            float s = unpackscore(my);
            bool valid = (s > (NEGV * 0.5f));
            unsigned int flat = ~((unsigned int)my);
            float4 bx = make_float4(-1.f, -1.f, -1.f, -1.f);
            float lab = -1.f;
            if (valid){
                bx  = gbox[s_idx[flat]];
                lab = (float)(flat / MAXDET);
            }
            obox  [b*MAXDET + rnk] = bx;
            oscore[b*MAXDET + rnk] = valid ? s : -1.f;
            olab  [b*MAXDET + rnk] = lab;
        }
    }
}

extern "C" void kernel_launch(void* const* d_in, const int* in_sizes, int n_in,
                              void* d_out, int out_size)
{
    const float* boxes = (const float*)d_in[0];
    const float* cls   = (const float*)d_in[1];
    if (n_in >= 2 && in_sizes[0] == Bc*Nc*Cc && in_sizes[1] == Bc*Nc*4){
        const float* tmp = boxes; boxes = cls; cls = tmp;
    }

    cudaFuncSetAttribute(nms_kernel, cudaFuncAttributeMaxDynamicSharedMemorySize, DYN_BYTES);
    cudaFuncSetAttribute(finalize_kernel, cudaFuncAttributeMaxDynamicSharedMemorySize, FIN_BYTES);

    nms_kernel<<<PAIRS*CS, TH, DYN_BYTES>>>(boxes, cls);
    finalize_kernel<<<Bc, 512, FIN_BYTES>>>(boxes, (float*)d_out);
}

// round 12
// speedup vs baseline: 1.0338x; 1.0338x over previous
#include <cuda_runtime.h>

// ---------------- problem constants (fixed shapes) ----------------
#define Bc 2
#define Nc 50000
#define Cc 15
#define PAIRS (Bc*Cc)          // 30
#define CS 4                   // cluster size (CTAs per (b,c) pair)
#define NPER (Nc/CS)           // 12500 candidates per CTA
#define TH 512
#define CPT 25                 // 25*512 = 12800 >= 12500
#define MAXDET 300
#define NEGV (-1e9f)
#define NK (Cc*MAXDET)         // 4500
#define NCAP 2048              // phase-2 list capacity per CTA
#define NRMAX 4                // NCAP/TH

// dynamic smem layout
#define OFF_BOXES 0            // float4[12800] = 204800 B
#define OFF_LIDX  204800       // u16[2048] = 4096 B
#define OFF_LSC   208896       // f32[2048] = 8192 B
#define DYN_BYTES 217088
#define FIN_BYTES (NK*12)

typedef unsigned long long u64;

// scratch (no allocations allowed -> __device__ globals)
__device__ int   g_pick_idx[PAIRS*MAXDET];
__device__ float g_pick_score[PAIRS*MAXDET];

// pack (score, index) into a u64 so that max() == (higher score, then LOWER index)
__device__ __forceinline__ u64 packkey(float s, unsigned int gidx){
    unsigned int sb = __float_as_uint(s);
    sb = (sb & 0x80000000u) ? ~sb : (sb | 0x80000000u);   // monotone float->uint
    return ((u64)sb << 32) | (unsigned int)(~gidx);
}
__device__ __forceinline__ float unpackscore(u64 k){
    unsigned int sb = (unsigned int)(k >> 32);
    return (sb & 0x80000000u) ? __uint_as_float(sb ^ 0x80000000u)
                              : __uint_as_float(~sb);
}
__device__ __forceinline__ void top2ins(u64 kk, u64 &m1, u64 &m2){
    if (kk > m1){ m2 = m1; m1 = kk; }
    else if (kk > m2){ m2 = kk; }
}
__device__ __forceinline__ void warp_top2(u64 &m1, u64 &m2){
    #pragma unroll
    for (int o = 16; o; o >>= 1){
        u64 o1 = __shfl_xor_sync(0xFFFFFFFFu, m1, o);
        u64 o2 = __shfl_xor_sync(0xFFFFFFFFu, m2, o);
        u64 hi = (m1 > o1) ? m1 : o1;
        u64 lo = (m1 > o1) ? o1 : m1;
        u64 mm = (m2 > o2) ? m2 : o2;
        m1 = hi;
        m2 = (lo > mm) ? lo : mm;
    }
}

extern __shared__ char s_dyn[];

__global__ void __cluster_dims__(CS,1,1) __launch_bounds__(TH,1)
nms_kernel(const float* __restrict__ boxes, const float* __restrict__ cls)
{
    float4*         s_boxes = reinterpret_cast<float4*>(s_dyn + OFF_BOXES);
    unsigned short* s_lidx  = reinterpret_cast<unsigned short*>(s_dyn + OFF_LIDX);
    float*          s_lsc   = reinterpret_cast<float*>(s_dyn + OFF_LSC);

    __shared__ u64 s_w1[16], s_w2[16];
    __shared__ u64 s_key [2][CS][2];   // double-buffered cluster exchange
    __shared__ __align__(16) float4 s_pbox[2][CS][2];
    __shared__ u64 s_mbar[2];
    __shared__ int s_icnt[16];
    __shared__ int s_wctr;

    const int pair = blockIdx.x >> 2;
    const int rank = blockIdx.x & 3;
    const int b = pair / Cc;
    const int c = pair % Cc;
    const int base = rank * NPER;
    const int t = threadIdx.x;
    const unsigned laneLT = (1u << (t & 31)) - 1u;

    const float4* gbox = reinterpret_cast<const float4*>(boxes) + (size_t)b * Nc;

    if (t == 0){
        s_wctr = 0;
        unsigned int m0 = (unsigned int)__cvta_generic_to_shared(&s_mbar[0]);
        unsigned int m1 = (unsigned int)__cvta_generic_to_shared(&s_mbar[1]);
        asm volatile("mbarrier.init.shared.b64 [%0], %1;" :: "r"(m0), "r"(CS) : "memory");
        asm volatile("mbarrier.init.shared.b64 [%0], %1;" :: "r"(m1), "r"(CS) : "memory");
    }

    // ---- load this CTA's boxes into SMEM (coalesced); zero OOB tail ----
    for (int i = t; i < NPER; i += TH) s_boxes[i] = gbox[base + i];
    for (int i = NPER + t; i < CPT*TH; i += TH) s_boxes[i] = make_float4(0.f,0.f,0.f,0.f);

    // ---- load + threshold scores into registers; cache areas ----
    float sc[CPT], ar[CPT];
    #pragma unroll
    for (int k = 0; k < CPT; k++){
        int li = k*TH + t;
        float s = NEGV;
        if (li < NPER){
            float v = cls[((size_t)(b*Nc + base + li))*Cc + c];
            if (v > 0.05f) s = v;
        }
        sc[k] = s;
    }
    __syncthreads();
    #pragma unroll
    for (int k = 0; k < CPT; k++){
        float4 bx = s_boxes[k*TH + t];
        ar[k] = (bx.z - bx.x) * (bx.w - bx.y);
    }

    // cluster sync: mbarrier inits visible cluster-wide before any remote arrive
    asm volatile("barrier.cluster.arrive.aligned;" ::: "memory");
    asm volatile("barrier.cluster.wait.aligned;"   ::: "memory");

    // ---- initial per-thread top-2 ----
    u64 myM1 = 0ull, myM2 = 0ull;
    #pragma unroll
    for (int k = 0; k < CPT; k++)
        top2ins(packkey(sc[k], (unsigned)(base + k*TH + t)), myM1, myM2);

    auto iou_gt = [](float4 P, float pa, float4 B, float ab) -> bool {
        float y1 = fmaxf(P.x, B.x), x1 = fmaxf(P.y, B.y);
        float y2 = fminf(P.z, B.z), x2 = fminf(P.w, B.w);
        float inter = fmaxf(y2 - y1, 0.f) * fmaxf(x2 - x1, 0.f);
        float denom = pa + ab - inter + 1e-9f;
        return __fdiv_rn(inter, denom) > 0.5f;
    };

    // ---- NMS rounds: 1 or 2 picks per round; phase 1 = register scan,
    //      phase 2 = per-CTA compact list scan (switch is per-CTA local) ----
    int det = 0, round = 0;
    int phase = 1, n = 0;
    while (det < MAXDET){
        const int pidx = round & 1;
        const unsigned par = (unsigned)((round >> 1) & 1);

        // CTA top-2 reduce
        u64 a1 = myM1, a2 = myM2;
        warp_top2(a1, a2);
        if ((t & 31) == 0){ s_w1[t >> 5] = a1; s_w2[t >> 5] = a2; }
        __syncthreads();
        if (t < 32){
            u64 c1 = (t < 16) ? s_w1[t] : 0ull;
            u64 c2 = (t < 16) ? s_w2[t] : 0ull;
            warp_top2(c1, c2);
            if (t < CS){
                unsigned int wloc1 = (~(unsigned int)c1) - (unsigned)base;
                unsigned int wloc2 = (~(unsigned int)c2) - (unsigned)base;
                float4 wb1 = s_boxes[wloc1];
                float4 wb2 = s_boxes[wloc2];
                u64 x01, x23, y01, y23;
                asm("mov.b64 %0, {%1,%2};" : "=l"(x01) : "f"(wb1.x), "f"(wb1.y));
                asm("mov.b64 %0, {%1,%2};" : "=l"(x23) : "f"(wb1.z), "f"(wb1.w));
                asm("mov.b64 %0, {%1,%2};" : "=l"(y01) : "f"(wb2.x), "f"(wb2.y));
                asm("mov.b64 %0, {%1,%2};" : "=l"(y23) : "f"(wb2.z), "f"(wb2.w));
                unsigned int lkey = (unsigned int)__cvta_generic_to_shared(&s_key [pidx][rank][0]);
                unsigned int lbox = (unsigned int)__cvta_generic_to_shared(&s_pbox[pidx][rank][0]);
                unsigned int lmb  = (unsigned int)__cvta_generic_to_shared(&s_mbar[pidx]);
                unsigned int rk, rb, rm;
                asm("mapa.shared::cluster.u32 %0, %1, %2;" : "=r"(rk) : "r"(lkey), "r"(t));
                asm("mapa.shared::cluster.u32 %0, %1, %2;" : "=r"(rb) : "r"(lbox), "r"(t));
                asm("mapa.shared::cluster.u32 %0, %1, %2;" : "=r"(rm) : "r"(lmb),  "r"(t));
                asm volatile("st.shared::cluster.u64 [%0], %1;"    :: "r"(rk), "l"(c1)  : "memory");
                asm volatile("st.shared::cluster.u64 [%0+8], %1;"  :: "r"(rk), "l"(c2)  : "memory");
                asm volatile("st.shared::cluster.u64 [%0], %1;"    :: "r"(rb), "l"(x01) : "memory");
                asm volatile("st.shared::cluster.u64 [%0+8], %1;"  :: "r"(rb), "l"(x23) : "memory");
                asm volatile("st.shared::cluster.u64 [%0+16], %1;" :: "r"(rb), "l"(y01) : "memory");
                asm volatile("st.shared::cluster.u64 [%0+24], %1;" :: "r"(rb), "l"(y23) : "memory");
                asm volatile("mbarrier.arrive.release.cluster.shared::cluster.b64 _, [%0];" :: "r"(rm) : "memory");
            }
        }
        // wait for all 4 CTAs (acquire orders remote stores)
        {
            unsigned int mloc = (unsigned int)__cvta_generic_to_shared(&s_mbar[pidx]);
            unsigned int done = 0;
            while (!done){
                asm volatile(
                    "{\n\t.reg .pred p;\n\t"
                    "mbarrier.try_wait.parity.acquire.cluster.shared::cta.b64 p, [%1], %2, 0x989680;\n\t"
                    "selp.b32 %0, 1, 0, p;\n\t}"
                    : "=r"(done) : "r"(mloc), "r"(par) : "memory");
            }
        }

        // global top-2 merge (identical on every thread of every CTA)
        u64 M1 = s_key[pidx][0][0]; int r1 = 0;
        #pragma unroll
        for (int r = 1; r < CS; r++){
            u64 v = s_key[pidx][r][0];
            if (v > M1){ M1 = v; r1 = r; }
        }
        u64 M2 = 0ull; int r2 = 0;
        #pragma unroll
        for (int r = 0; r < CS; r++){
            u64 v = (r == r1) ? s_key[pidx][r][1] : s_key[pidx][r][0];
            if (v > M2){ M2 = v; r2 = r; }
        }
        const int slot2 = (r2 == r1) ? 1 : 0;
        float4 B1 = s_pbox[pidx][r1][0];
        float4 B2 = s_pbox[pidx][r2][slot2];

        const unsigned int widx1 = ~((unsigned int)M1);
        const float pa1 = (B1.z - B1.x) * (B1.w - B1.y);
        const float score2 = unpackscore(M2);

        bool dual = false;
        float pa2 = pa1;
        if (score2 != NEGV && det + 1 < MAXDET){
            float a2f = (B2.z - B2.x) * (B2.w - B2.y);
            if (!iou_gt(B1, pa1, B2, a2f)){ dual = true; pa2 = a2f; }
        }
        const unsigned int widx2 = dual ? ~((unsigned int)M2) : widx1;

        if (rank == 0 && t == 0){
            g_pick_idx  [pair*MAXDET + det] = (int)widx1;
            g_pick_score[pair*MAXDET + det] = unpackscore(M1);
            if (dual){
                g_pick_idx  [pair*MAXDET + det + 1] = (int)widx2;
                g_pick_score[pair*MAXDET + det + 1] = score2;
            }
        }
        if (!dual) B2 = B1;

        if (phase == 1){
            // ---------------- PHASE 1: register scan (R8 structure) ----------------
            const unsigned int wl1 = widx1 - (unsigned)base;
            const int W1 = ((wl1 & (TH-1)) == (unsigned)t) ? (int)(wl1 >> 9) : -1;
            int W2 = -1;
            if (dual){
                unsigned int wl2 = widx2 - (unsigned)base;
                W2 = ((wl2 & (TH-1)) == (unsigned)t) ? (int)(wl2 >> 9) : -1;
            }

            unsigned band1 = 0, band2 = 0;
            if (dual){
                #pragma unroll
                for (int k = 0; k < CPT; k++){
                    float s = sc[k];
                    bool alive = (s != NEGV);
                    float4 bx = make_float4(0.f,0.f,0.f,0.f);
                    if (alive) bx = s_boxes[k*TH + t];
                    float p1y1 = fmaxf(B1.x, bx.x), p1x1 = fmaxf(B1.y, bx.y);
                    float p1y2 = fminf(B1.z, bx.z), p1x2 = fminf(B1.w, bx.w);
                    float in1 = fmaxf(p1y2 - p1y1, 0.f) * fmaxf(p1x2 - p1x1, 0.f);
                    float dn1 = pa1 + ar[k] - in1 + 1e-9f;
                    float ii1 = in1 + in1;
                    bool ab1 = (ii1 > 1.0001f * dn1);
                    bool bl1 = (ii1 < 0.9999f * dn1);
                    float p2y1 = fmaxf(B2.x, bx.x), p2x1 = fmaxf(B2.y, bx.y);
                    float p2y2 = fminf(B2.z, bx.z), p2x2 = fminf(B2.w, bx.w);
                    float in2 = fmaxf(p2y2 - p2y1, 0.f) * fmaxf(p2x2 - p2x1, 0.f);
                    float dn2 = pa2 + ar[k] - in2 + 1e-9f;
                    float ii2 = in2 + in2;
                    bool ab2 = (ii2 > 1.0001f * dn2);
                    bool bl2 = (ii2 < 0.9999f * dn2);
                    band1 |= (alive && !ab1 && !bl1) ? (1u << k) : 0u;
                    band2 |= (alive && !ab2 && !bl2) ? (1u << k) : 0u;
                    bool supf = alive && (ab1 || ab2 || (k == W1) || (k == W2));
                    sc[k] = supf ? NEGV : s;
                }
            } else {
                #pragma unroll
                for (int k = 0; k < CPT; k++){
                    float s = sc[k];
                    bool alive = (s != NEGV);
                    float4 bx = make_float4(0.f,0.f,0.f,0.f);
                    if (alive) bx = s_boxes[k*TH + t];
                    float y1 = fmaxf(B1.x, bx.x), x1 = fmaxf(B1.y, bx.y);
                    float y2 = fminf(B1.z, bx.z), x2 = fminf(B1.w, bx.w);
                    float inter = fmaxf(y2 - y1, 0.f) * fmaxf(x2 - x1, 0.f);
                    float denom = pa1 + ar[k] - inter + 1e-9f;
                    float ii = inter + inter;
                    bool ab = (ii > 1.0001f * denom);
                    bool bl = (ii < 0.9999f * denom);
                    band1 |= (alive && !ab && !bl) ? (1u << k) : 0u;
                    bool supf = alive && (ab || (k == W1));
                    sc[k] = supf ? NEGV : s;
                }
            }

            // rare exact-division fixup (warp-uniform outer branch)
            if (__any_sync(0xFFFFFFFFu, (band1 | band2) != 0)){
                unsigned bb = band1 | band2;
                #pragma unroll 1
                for (int k = 0; k < CPT; k++){
                    if (bb & (1u << k)){
                        float4 bx = s_boxes[k*TH + t];
                        bool sup = false;
                        if (band1 & (1u << k)) sup |= iou_gt(B1, pa1, bx, ar[k]);
                        if (band2 & (1u << k)) sup |= iou_gt(B2, pa2, bx, ar[k]);
                        if (sup) sc[k] = NEGV;
                    }
                }
            }

            // fresh per-thread top-2
            u64 m1 = 0ull, m2 = 0ull;
            #pragma unroll
            for (int k = 0; k < CPT; k++)
                top2ins(packkey(sc[k], (unsigned)(base + k*TH + t)), m1, m2);
            myM1 = m1; myM2 = m2;

            // every 8th round: per-CTA alive count; switch when it fits the list
            if ((round & 7) == 7){
                int myAlive = 0;
                #pragma unroll
                for (int k = 0; k < CPT; k++) if (sc[k] != NEGV) myAlive++;
                unsigned nw = __reduce_add_sync(0xFFFFFFFFu, (unsigned)myAlive);
                if ((t & 31) == 0) s_icnt[t >> 5] = (int)nw;
                __syncthreads();
                int tot = 0;
                #pragma unroll
                for (int i = 0; i < 16; i++) tot += s_icnt[i];
                if (tot <= NCAP){
                    // build compact list (order arbitrary; keys carry tie-break)
                    #pragma unroll 1
                    for (int k = 0; k < CPT; k++){
                        bool kp = (sc[k] != NEGV);
                        unsigned m = __ballot_sync(0xFFFFFFFFu, kp);
                        if (m){
                            int rin = __popc(m & laneLT);
                            int leader = __ffs(m) - 1;
                            int posBase = 0;
                            if ((t & 31) == leader) posBase = atomicAdd(&s_wctr, __popc(m));
                            posBase = __shfl_sync(0xFFFFFFFFu, posBase, leader);
                            if (kp){
                                s_lidx[posBase + rin] = (unsigned short)(k*TH + t);
                                s_lsc [posBase + rin] = sc[k];
                            }
                        }
                    }
                    __syncthreads();
                    n = s_wctr;
                    phase = 2;
                }
            }
        } else {
            // ---------------- PHASE 2: compact list scan ----------------
            u64 m1 = 0ull, m2 = 0ull;
            for (int e = t; e < n; e += TH){
                int li = (int)s_lidx[e];
                float s = s_lsc[e];
                bool alive = (s != NEGV);
                float4 bx = s_boxes[li];
                float ak = (bx.z - bx.x) * (bx.w - bx.y);
                unsigned gi = (unsigned)(base + li);
                bool sup = alive && (iou_gt(B1, pa1, bx, ak) ||
                                     iou_gt(B2, pa2, bx, ak) ||
                                     (gi == widx1) || (gi == widx2));
                float ns = sup ? NEGV : s;
                if (sup) s_lsc[e] = NEGV;
                top2ins(packkey(ns, gi), m1, m2);
            }
            myM1 = m1; myM2 = m2;

            // amortized compaction every 16 rounds
            if ((round & 15) == 15 && n > 0){
                unsigned short rli[NRMAX]; float rsc[NRMAX];
                int cnt = 0;
                for (int e = t; e < n; e += TH){
                    float s = s_lsc[e];
                    if (s != NEGV){ rli[cnt] = s_lidx[e]; rsc[cnt] = s; cnt++; }
                }
                if (t == 0) s_wctr = 0;
                __syncthreads();
                int pos = (cnt > 0) ? atomicAdd(&s_wctr, cnt) : 0;
                for (int i = 0; i < cnt; i++){
                    s_lidx[pos + i] = rli[i];
                    s_lsc [pos + i] = rsc[i];
                }
                __syncthreads();
                n = s_wctr;
            }
        }

        det += dual ? 2 : 1;
        round++;
    }

    // trailing sync so no CTA exits while peers may still address its SMEM
    asm volatile("barrier.cluster.arrive.aligned;" ::: "memory");
    asm volatile("barrier.cluster.wait.aligned;"   ::: "memory");
}

// ---------------- per-image top-300 via per-key global rank ----------------
extern __shared__ char f_dyn[];
__global__ void __launch_bounds__(512)
finalize_kernel(const float* __restrict__ boxes, float* __restrict__ out)
{
    u64* s_keys = reinterpret_cast<u64*>(f_dyn);
    int* s_idx = reinterpret_cast<int*>(f_dyn + NK*8);

    const int b = blockIdx.x;
    const int t = threadIdx.x;

    for (int i = t; i < NK; i += 512){
        s_keys[i] = packkey(g_pick_score[b*NK + i], (unsigned)i);
        s_idx[i]  = g_pick_idx[b*NK + i];
    }
    __syncthreads();

    const float4* gbox = reinterpret_cast<const float4*>(boxes) + (size_t)b * Nc;
    float4* obox   = reinterpret_cast<float4*>(out);
    float*  oscore = out + (size_t)Bc*MAXDET*4;
    float*  olab   = out + (size_t)Bc*MAXDET*5;

    for (int i = t; i < NK; i += 512){
        u64 my = s_keys[i];
        int rnk = 0;
        #pragma unroll
        for (int c = 0; c < Cc; c++){
            int lo = 0, hi = MAXDET;
            while (lo < hi){                       // 9 data-independent steps
                int mid = (lo + hi) >> 1;
                if (s_keys[c*MAXDET + mid] > my) lo = mid + 1; else hi = mid;
            }
            rnk += lo;
        }
        if (rnk < MAXDET){
            float s = unpackscore(my);
            bool valid = (s > (NEGV * 0.5f));
            unsigned int flat = ~((unsigned int)my);
            float4 bx = make_float4(-1.f, -1.f, -1.f, -1.f);
            float lab = -1.f;
            if (valid){
                bx  = gbox[s_idx[flat]];
                lab = (float)(flat / MAXDET);
            }
            obox  [b*MAXDET + rnk] = bx;
            oscore[b*MAXDET + rnk] = valid ? s : -1.f;
            olab  [b*MAXDET + rnk] = lab;
        }
    }
}

extern "C" void kernel_launch(void* const* d_in, const int* in_sizes, int n_in,
                              void* d_out, int out_size)
{
    const float* boxes = (const float*)d_in[0];
    const float* cls   = (const float*)d_in[1];
    if (n_in >= 2 && in_sizes[0] == Bc*Nc*Cc && in_sizes[1] == Bc*Nc*4){
        const float* tmp = boxes; boxes = cls; cls = tmp;
    }

    cudaFuncSetAttribute(nms_kernel, cudaFuncAttributeMaxDynamicSharedMemorySize, DYN_BYTES);
    cudaFuncSetAttribute(finalize_kernel, cudaFuncAttributeMaxDynamicSharedMemorySize, FIN_BYTES);

    nms_kernel<<<PAIRS*CS, TH, DYN_BYTES>>>(boxes, cls);
    finalize_kernel<<<Bc, 512, FIN_BYTES>>>(boxes, (float*)d_out);
}